// round 10
// baseline (speedup 1.0000x reference)
#include <cuda_runtime.h>

#define NN 100000
#define EE 3200000

// ---------------- device scratch (no allocations allowed) ----------------
__device__ float g_q[(size_t)NN * 512];       // [node][head][128] fp32
__device__ float g_k[(size_t)NN * 512];       // [node][head][128] fp32
__device__ float g_scores[(size_t)EE * 4];    // CSR-ordered scores, 4 heads
__device__ int   g_deg[NN];
__device__ int   g_off[NN + 1];
__device__ int   g_cur[NN];
__device__ int   g_ccol[EE];                  // source node per CSR slot
__device__ int   g_ceid[EE];                  // original edge id per CSR slot

// ---------------- GEMM: qk = x @ W^T + b, split into g_q / g_k ----------------
// 128x128 tile, K=128 entirely in smem (128 KB dynamic), 256 threads, 8x8 microtile.
__global__ __launch_bounds__(256) void gemm_qk_kernel(
    const float* __restrict__ x, const float* __restrict__ W,
    const float* __restrict__ bias, int nrows)
{
    extern __shared__ float smem[];
    float* As = smem;           // As[k*128 + m] = x[row0+m][k]
    float* Bs = smem + 16384;   // Bs[k*128 + n] = W[col0+n][k]

    const int t = threadIdx.x;
    const int row0 = blockIdx.y << 7;
    const int col0 = blockIdx.x << 7;

    // --- load + transpose (conflict-free stores: bank = m mod 32, distinct per lane) ---
    {
        const int m = t & 127;
        const int half = t >> 7;           // 0/1
        const int arow = row0 + m;
        const bool rok = arow < nrows;
        const float4* xr = (const float4*)(x + (size_t)arow * 128);
        const float4* wr = (const float4*)(W + (size_t)(col0 + m) * 128);
#pragma unroll
        for (int it = 0; it < 16; ++it) {
            int k4 = half + (it << 1);     // 0..31
            int kk = k4 << 2;
            float4 v = rok ? xr[k4] : make_float4(0.f, 0.f, 0.f, 0.f);
            As[(kk    ) * 128 + m] = v.x;
            As[(kk + 1) * 128 + m] = v.y;
            As[(kk + 2) * 128 + m] = v.z;
            As[(kk + 3) * 128 + m] = v.w;
            float4 w4 = wr[k4];
            Bs[(kk    ) * 128 + m] = w4.x;
            Bs[(kk + 1) * 128 + m] = w4.y;
            Bs[(kk + 2) * 128 + m] = w4.z;
            Bs[(kk + 3) * 128 + m] = w4.w;
        }
    }
    __syncthreads();

    const int tx = t & 15, ty = t >> 4;
    float acc[8][8];
#pragma unroll
    for (int i = 0; i < 8; ++i)
#pragma unroll
        for (int j = 0; j < 8; ++j) acc[i][j] = 0.f;

#pragma unroll 4
    for (int k = 0; k < 128; ++k) {
        float4 a0 = *(const float4*)&As[k * 128 + (ty << 2)];
        float4 a1 = *(const float4*)&As[k * 128 + 64 + (ty << 2)];
        float4 b0 = *(const float4*)&Bs[k * 128 + (tx << 2)];
        float4 b1 = *(const float4*)&Bs[k * 128 + 64 + (tx << 2)];
        float a[8] = {a0.x, a0.y, a0.z, a0.w, a1.x, a1.y, a1.z, a1.w};
        float bb[8] = {b0.x, b0.y, b0.z, b0.w, b1.x, b1.y, b1.z, b1.w};
#pragma unroll
        for (int i = 0; i < 8; ++i)
#pragma unroll
            for (int j = 0; j < 8; ++j)
                acc[i][j] = fmaf(a[i], bb[j], acc[i][j]);
    }

    // --- epilogue: this 128-col tile is exactly one (head, q-or-k) slab ---
    const int h = col0 >> 8;
    float* dst = (col0 & 128) ? g_k : g_q;
    float4 bb0 = *(const float4*)&bias[col0 + (tx << 2)];
    float4 bb1 = *(const float4*)&bias[col0 + 64 + (tx << 2)];
#pragma unroll
    for (int i = 0; i < 8; ++i) {
        int rr = (i < 4) ? ((ty << 2) + i) : (64 + (ty << 2) + (i - 4));
        int row = row0 + rr;
        if (row < nrows) {
            float* p = dst + ((size_t)(row * 4 + h) << 7);
            float4 v0 = make_float4(acc[i][0] + bb0.x, acc[i][1] + bb0.y,
                                    acc[i][2] + bb0.z, acc[i][3] + bb0.w);
            float4 v1 = make_float4(acc[i][4] + bb1.x, acc[i][5] + bb1.y,
                                    acc[i][6] + bb1.z, acc[i][7] + bb1.w);
            *(float4*)(p + (tx << 2)) = v0;
            *(float4*)(p + 64 + (tx << 2)) = v1;
        }
    }
}

// ---------------- CSR build (edge_index is INT32: jax default x64-disabled) ----
__global__ void zero_deg_kernel(int n) {
    int i = blockIdx.x * blockDim.x + threadIdx.x;
    if (i < n) g_deg[i] = 0;
}

__global__ void hist_kernel(const int* __restrict__ ei, int E) {
    int stride = gridDim.x * blockDim.x;
    for (int e = blockIdx.x * blockDim.x + threadIdx.x; e < E; e += stride)
        atomicAdd(&g_deg[ei[e]], 1);
}

__global__ __launch_bounds__(1024) void scan_kernel(int n) {
    __shared__ int sh[1024];
    const int t = threadIdx.x;
    const int per = (n + 1023) >> 10;
    const int lo = t * per;
    const int hi = min(lo + per, n);
    int s = 0;
    for (int i = lo; i < hi; ++i) s += g_deg[i];
    sh[t] = s;
    __syncthreads();
    for (int off = 1; off < 1024; off <<= 1) {
        int v = (t >= off) ? sh[t - off] : 0;
        __syncthreads();
        sh[t] += v;
        __syncthreads();
    }
    int run = sh[t] - s;   // exclusive prefix
    for (int i = lo; i < hi; ++i) {
        g_off[i] = run;
        g_cur[i] = run;
        run += g_deg[i];
    }
    if (t == 1023) g_off[n] = sh[1023];
}

__global__ void scatter_kernel(const int* __restrict__ ei, int E) {
    int stride = gridDim.x * blockDim.x;
    for (int e = blockIdx.x * blockDim.x + threadIdx.x; e < E; e += stride) {
        int r = ei[e];
        int c = ei[E + e];
        int p = atomicAdd(&g_cur[r], 1);
        g_ccol[p] = c;
        g_ceid[p] = e;
    }
}

// ---------------- per-node attention: scores + segment softmax + head mean ----------------
// One block (128 thr) per node. Warp w = head w. Within a warp: 4 groups of 8
// lanes process 4 edges concurrently; each lane covers 16 contiguous floats.
__global__ __launch_bounds__(128) void attn_kernel(float* __restrict__ out)
{
    const int r = blockIdx.x;
    const int beg = g_off[r];
    const int deg = g_off[r + 1] - beg;
    if (deg == 0) return;

    const int warp = threadIdx.x >> 5;
    const int lane = threadIdx.x & 31;
    const int grp = lane >> 3;   // which of 4 edges
    const int gl  = lane & 7;    // slice within edge

    __shared__ float sm_m[4], sm_s[4];

    const float4* qb = (const float4*)(g_q + ((size_t)(r * 4 + warp) << 7));
    const float4 q0 = qb[(gl << 2) + 0];
    const float4 q1 = qb[(gl << 2) + 1];
    const float4 q2 = qb[(gl << 2) + 2];
    const float4 q3 = qb[(gl << 2) + 3];

    float rmax = -3.4e38f;
    for (int i = 0; i < deg; i += 4) {
        int ii = i + grp;
        bool valid = ii < deg;
        int c = g_ccol[beg + (valid ? ii : 0)];
        const float4* kb = (const float4*)(g_k + ((size_t)(c * 4 + warp) << 7));
        float4 k0 = kb[(gl << 2) + 0];
        float4 k1 = kb[(gl << 2) + 1];
        float4 k2 = kb[(gl << 2) + 2];
        float4 k3 = kb[(gl << 2) + 3];
        float s = 0.f;
        s = fmaf(q0.x, k0.x, s); s = fmaf(q0.y, k0.y, s);
        s = fmaf(q0.z, k0.z, s); s = fmaf(q0.w, k0.w, s);
        s = fmaf(q1.x, k1.x, s); s = fmaf(q1.y, k1.y, s);
        s = fmaf(q1.z, k1.z, s); s = fmaf(q1.w, k1.w, s);
        s = fmaf(q2.x, k2.x, s); s = fmaf(q2.y, k2.y, s);
        s = fmaf(q2.z, k2.z, s); s = fmaf(q2.w, k2.w, s);
        s = fmaf(q3.x, k3.x, s); s = fmaf(q3.y, k3.y, s);
        s = fmaf(q3.z, k3.z, s); s = fmaf(q3.w, k3.w, s);
        // reduce 8-lane slices (3 shfls serve all 4 edges at once)
        s += __shfl_xor_sync(0xffffffffu, s, 1);
        s += __shfl_xor_sync(0xffffffffu, s, 2);
        s += __shfl_xor_sync(0xffffffffu, s, 4);
        if (valid && gl == 0) {
            g_scores[(size_t)(beg + ii) * 4 + warp] = s;
            rmax = fmaxf(rmax, s);
        }
    }
#pragma unroll
    for (int o = 16; o > 0; o >>= 1)
        rmax = fmaxf(rmax, __shfl_xor_sync(0xffffffffu, rmax, o));

    float ssum = 0.f;
    for (int i = lane; i < deg; i += 32)
        ssum += __expf(g_scores[(size_t)(beg + i) * 4 + warp] - rmax);
#pragma unroll
    for (int o = 16; o > 0; o >>= 1)
        ssum += __shfl_xor_sync(0xffffffffu, ssum, o);

    if (lane == 0) { sm_m[warp] = rmax; sm_s[warp] = 1.f / ssum; }
    __syncthreads();

    const float m0 = sm_m[0], m1 = sm_m[1], m2 = sm_m[2], m3 = sm_m[3];
    const float s0 = sm_s[0], s1 = sm_s[1], s2 = sm_s[2], s3 = sm_s[3];
    for (int i = threadIdx.x; i < deg; i += 128) {
        float4 sc = *(const float4*)(g_scores + (size_t)(beg + i) * 4);
        float a = __expf(sc.x - m0) * s0 + __expf(sc.y - m1) * s1 +
                  __expf(sc.z - m2) * s2 + __expf(sc.w - m3) * s3;
        out[g_ceid[beg + i]] = 0.25f * a;
    }
}

// ---------------- launch ----------------
extern "C" void kernel_launch(void* const* d_in, const int* in_sizes, int n_in,
                              void* d_out, int out_size)
{
    const float* x    = (const float*)d_in[0];      // [N,128]
    const float* W    = (const float*)d_in[1];      // [1024,128]
    const float* bias = (const float*)d_in[2];      // [1024]
    const int*   ei   = (const int*)d_in[3];        // [2,E] int32 (jax x64 off)
    float* out = (float*)d_out;

    const int N = in_sizes[0] / 128;
    const int E = in_sizes[3] / 2;

    cudaFuncSetAttribute(gemm_qk_kernel,
                         cudaFuncAttributeMaxDynamicSharedMemorySize, 131072);

    dim3 gg(8, (N + 127) / 128);
    gemm_qk_kernel<<<gg, 256, 131072>>>(x, W, bias, N);

    zero_deg_kernel<<<(N + 255) / 256, 256>>>(N);
    hist_kernel<<<2048, 256>>>(ei, E);
    scan_kernel<<<1, 1024>>>(N);
    scatter_kernel<<<2048, 256>>>(ei, E);
    attn_kernel<<<N, 128>>>(out);
}

// round 11
// speedup vs baseline: 1.0718x; 1.0718x over previous
#include <cuda_runtime.h>

#define NN 100000
#define EE 3200000

// ---------------- device scratch (no allocations allowed) ----------------
__device__ float g_q[(size_t)NN * 512];       // [node][head][128] fp32
__device__ float g_k[(size_t)NN * 512];       // [node][head][128] fp32
__device__ float g_scores[(size_t)EE * 4];    // CSR-ordered scores, 4 heads
__device__ int   g_deg[NN];
__device__ int   g_off[NN + 1];
__device__ int   g_cur[NN];
__device__ int   g_ccol[EE];                  // source node per CSR slot
__device__ int   g_ceid[EE];                  // original edge id per CSR slot
__device__ int   g_bsum[64];                  // scan block sums
__device__ int   g_bpre[64];                  // scan block exclusive prefixes

// ---------------- GEMM: qk = x @ W^T + b, split into g_q / g_k ----------------
// 128x128 tile, K=128 entirely in smem (128 KB dynamic), 256 threads, 8x8 microtile.
// Mainloop uses packed fp32x2 FMA (FFMA2): B columns paired as 64-bit lanes
// loaded straight from smem; A scalars duplicated into pairs with mov.b64.
__global__ __launch_bounds__(256) void gemm_qk_kernel(
    const float* __restrict__ x, const float* __restrict__ W,
    const float* __restrict__ bias, int nrows)
{
    extern __shared__ float smem[];
    float* As = smem;           // As[k*128 + m] = x[row0+m][k]
    float* Bs = smem + 16384;   // Bs[k*128 + n] = W[col0+n][k]

    const int t = threadIdx.x;
    const int row0 = blockIdx.y << 7;
    const int col0 = blockIdx.x << 7;

    // --- load + transpose (conflict-free stores: bank = m mod 32, distinct per lane) ---
    {
        const int m = t & 127;
        const int half = t >> 7;           // 0/1
        const int arow = row0 + m;
        const bool rok = arow < nrows;
        const float4* xr = (const float4*)(x + (size_t)arow * 128);
        const float4* wr = (const float4*)(W + (size_t)(col0 + m) * 128);
#pragma unroll
        for (int it = 0; it < 16; ++it) {
            int k4 = half + (it << 1);     // 0..31
            int kk = k4 << 2;
            float4 v = rok ? xr[k4] : make_float4(0.f, 0.f, 0.f, 0.f);
            As[(kk    ) * 128 + m] = v.x;
            As[(kk + 1) * 128 + m] = v.y;
            As[(kk + 2) * 128 + m] = v.z;
            As[(kk + 3) * 128 + m] = v.w;
            float4 w4 = wr[k4];
            Bs[(kk    ) * 128 + m] = w4.x;
            Bs[(kk + 1) * 128 + m] = w4.y;
            Bs[(kk + 2) * 128 + m] = w4.z;
            Bs[(kk + 3) * 128 + m] = w4.w;
        }
    }
    __syncthreads();

    const int tx = t & 15, ty = t >> 4;

    // acc2[i][j] packs output columns (2j, 2j+1) of the thread's 8-col strip:
    // j=0,1 -> cols tx*4+{0,1},{2,3}; j=2,3 -> cols 64+tx*4+{0,1},{2,3}
    unsigned long long acc2[8][4];
#pragma unroll
    for (int i = 0; i < 8; ++i)
#pragma unroll
        for (int j = 0; j < 4; ++j) acc2[i][j] = 0ULL;

#pragma unroll 4
    for (int k = 0; k < 128; ++k) {
        float4 a0 = *(const float4*)&As[k * 128 + (ty << 2)];
        float4 a1 = *(const float4*)&As[k * 128 + 64 + (ty << 2)];
        float a[8] = {a0.x, a0.y, a0.z, a0.w, a1.x, a1.y, a1.z, a1.w};

        // B pairs loaded directly as 64-bit lanes (16B-aligned smem)
        ulonglong2 bp0 = *(const ulonglong2*)&Bs[k * 128 + (tx << 2)];
        ulonglong2 bp1 = *(const ulonglong2*)&Bs[k * 128 + 64 + (tx << 2)];
        unsigned long long bp[4] = {bp0.x, bp0.y, bp1.x, bp1.y};

        unsigned long long ap[8];
#pragma unroll
        for (int i = 0; i < 8; ++i)
            asm("mov.b64 %0, {%1, %1};" : "=l"(ap[i]) : "f"(a[i]));

#pragma unroll
        for (int i = 0; i < 8; ++i)
#pragma unroll
            for (int j = 0; j < 4; ++j)
                asm("fma.rn.f32x2 %0, %1, %2, %0;"
                    : "+l"(acc2[i][j]) : "l"(ap[i]), "l"(bp[j]));
    }

    // --- epilogue: this 128-col tile is exactly one (head, q-or-k) slab ---
    const int h = col0 >> 8;
    float* dst = (col0 & 128) ? g_k : g_q;
    float4 bb0 = *(const float4*)&bias[col0 + (tx << 2)];
    float4 bb1 = *(const float4*)&bias[col0 + 64 + (tx << 2)];
#pragma unroll
    for (int i = 0; i < 8; ++i) {
        int rr = (i < 4) ? ((ty << 2) + i) : (64 + (ty << 2) + (i - 4));
        int row = row0 + rr;
        if (row < nrows) {
            float* p = dst + ((size_t)(row * 4 + h) << 7);
            float c0, c1, c2, c3, c4, c5, c6, c7;
            asm("mov.b64 {%0, %1}, %2;" : "=f"(c0), "=f"(c1) : "l"(acc2[i][0]));
            asm("mov.b64 {%0, %1}, %2;" : "=f"(c2), "=f"(c3) : "l"(acc2[i][1]));
            asm("mov.b64 {%0, %1}, %2;" : "=f"(c4), "=f"(c5) : "l"(acc2[i][2]));
            asm("mov.b64 {%0, %1}, %2;" : "=f"(c6), "=f"(c7) : "l"(acc2[i][3]));
            float4 v0 = make_float4(c0 + bb0.x, c1 + bb0.y, c2 + bb0.z, c3 + bb0.w);
            float4 v1 = make_float4(c4 + bb1.x, c5 + bb1.y, c6 + bb1.z, c7 + bb1.w);
            *(float4*)(p + (tx << 2)) = v0;
            *(float4*)(p + 64 + (tx << 2)) = v1;
        }
    }
}

// ---------------- CSR build (edge_index is INT32: jax default x64-disabled) ----
__global__ void zero_deg_kernel(int n) {
    int i = blockIdx.x * blockDim.x + threadIdx.x;
    if (i < n) g_deg[i] = 0;
}

__global__ void hist_kernel(const int* __restrict__ ei, int E) {
    int stride = gridDim.x * blockDim.x;
    for (int e = blockIdx.x * blockDim.x + threadIdx.x; e < E; e += stride)
        atomicAdd(&g_deg[ei[e]], 1);
}

// ---- parallel 3-phase exclusive scan of g_deg -> g_off / g_cur ----
#define SCAN_BLK 1024
#define SCAN_CHUNK 2048   // 2 elements per thread

__global__ __launch_bounds__(SCAN_BLK) void scan_reduce_kernel(int n) {
    __shared__ int sh[SCAN_BLK];
    const int blk = blockIdx.x, t = threadIdx.x;
    const int i0 = blk * SCAN_CHUNK + 2 * t;
    int s = 0;
    if (i0 < n)     s += g_deg[i0];
    if (i0 + 1 < n) s += g_deg[i0 + 1];
    sh[t] = s;
    __syncthreads();
#pragma unroll
    for (int o = SCAN_BLK / 2; o > 0; o >>= 1) {
        if (t < o) sh[t] += sh[t + o];
        __syncthreads();
    }
    if (t == 0) g_bsum[blk] = sh[0];
}

__global__ void scan_top_kernel(int nb, int n) {
    __shared__ int sh[64];
    const int t = threadIdx.x;      // 64 threads
    int v = (t < nb) ? g_bsum[t] : 0;
    sh[t] = v;
    __syncthreads();
#pragma unroll
    for (int o = 1; o < 64; o <<= 1) {
        int u = (t >= o) ? sh[t - o] : 0;
        __syncthreads();
        sh[t] += u;
        __syncthreads();
    }
    if (t < nb) g_bpre[t] = sh[t] - v;   // exclusive
    if (t == 63) g_off[n] = sh[63];      // total edge count
}

__global__ __launch_bounds__(SCAN_BLK) void scan_write_kernel(int n) {
    __shared__ int sh[SCAN_BLK];
    const int blk = blockIdx.x, t = threadIdx.x;
    const int i0 = blk * SCAN_CHUNK + 2 * t;
    int d0 = 0, d1 = 0;
    if (i0 < n)     d0 = g_deg[i0];
    if (i0 + 1 < n) d1 = g_deg[i0 + 1];
    int s = d0 + d1;
    sh[t] = s;
    __syncthreads();
#pragma unroll
    for (int o = 1; o < SCAN_BLK; o <<= 1) {
        int u = (t >= o) ? sh[t - o] : 0;
        __syncthreads();
        sh[t] += u;
        __syncthreads();
    }
    int excl = sh[t] - s + g_bpre[blk];
    if (i0 < n)     { g_off[i0]     = excl;      g_cur[i0]     = excl;      }
    if (i0 + 1 < n) { g_off[i0 + 1] = excl + d0; g_cur[i0 + 1] = excl + d0; }
}

__global__ void scatter_kernel(const int* __restrict__ ei, int E) {
    int stride = gridDim.x * blockDim.x;
    for (int e = blockIdx.x * blockDim.x + threadIdx.x; e < E; e += stride) {
        int r = ei[e];
        int c = ei[E + e];
        int p = atomicAdd(&g_cur[r], 1);
        g_ccol[p] = c;
        g_ceid[p] = e;
    }
}

// ---------------- per-node attention: scores + segment softmax + head mean ----------------
// One block (128 thr) per node. Warp w = head w. Within a warp: 4 groups of 8
// lanes process 4 edges concurrently; each lane covers 16 contiguous floats.
__global__ __launch_bounds__(128) void attn_kernel(float* __restrict__ out)
{
    const int r = blockIdx.x;
    const int beg = g_off[r];
    const int deg = g_off[r + 1] - beg;
    if (deg == 0) return;

    const int warp = threadIdx.x >> 5;
    const int lane = threadIdx.x & 31;
    const int grp = lane >> 3;   // which of 4 edges
    const int gl  = lane & 7;    // slice within edge

    __shared__ float sm_m[4], sm_s[4];

    const float4* qb = (const float4*)(g_q + ((size_t)(r * 4 + warp) << 7));
    const float4 q0 = qb[(gl << 2) + 0];
    const float4 q1 = qb[(gl << 2) + 1];
    const float4 q2 = qb[(gl << 2) + 2];
    const float4 q3 = qb[(gl << 2) + 3];

    float rmax = -3.4e38f;
    for (int i = 0; i < deg; i += 4) {
        int ii = i + grp;
        bool valid = ii < deg;
        int c = g_ccol[beg + (valid ? ii : 0)];
        const float4* kb = (const float4*)(g_k + ((size_t)(c * 4 + warp) << 7));
        float4 k0 = kb[(gl << 2) + 0];
        float4 k1 = kb[(gl << 2) + 1];
        float4 k2 = kb[(gl << 2) + 2];
        float4 k3 = kb[(gl << 2) + 3];
        float s = 0.f;
        s = fmaf(q0.x, k0.x, s); s = fmaf(q0.y, k0.y, s);
        s = fmaf(q0.z, k0.z, s); s = fmaf(q0.w, k0.w, s);
        s = fmaf(q1.x, k1.x, s); s = fmaf(q1.y, k1.y, s);
        s = fmaf(q1.z, k1.z, s); s = fmaf(q1.w, k1.w, s);
        s = fmaf(q2.x, k2.x, s); s = fmaf(q2.y, k2.y, s);
        s = fmaf(q2.z, k2.z, s); s = fmaf(q2.w, k2.w, s);
        s = fmaf(q3.x, k3.x, s); s = fmaf(q3.y, k3.y, s);
        s = fmaf(q3.z, k3.z, s); s = fmaf(q3.w, k3.w, s);
        // reduce 8-lane slices (3 shfls serve all 4 edges at once)
        s += __shfl_xor_sync(0xffffffffu, s, 1);
        s += __shfl_xor_sync(0xffffffffu, s, 2);
        s += __shfl_xor_sync(0xffffffffu, s, 4);
        if (valid && gl == 0) {
            g_scores[(size_t)(beg + ii) * 4 + warp] = s;
            rmax = fmaxf(rmax, s);
        }
    }
#pragma unroll
    for (int o = 16; o > 0; o >>= 1)
        rmax = fmaxf(rmax, __shfl_xor_sync(0xffffffffu, rmax, o));

    float ssum = 0.f;
    for (int i = lane; i < deg; i += 32)
        ssum += __expf(g_scores[(size_t)(beg + i) * 4 + warp] - rmax);
#pragma unroll
    for (int o = 16; o > 0; o >>= 1)
        ssum += __shfl_xor_sync(0xffffffffu, ssum, o);

    if (lane == 0) { sm_m[warp] = rmax; sm_s[warp] = 1.f / ssum; }
    __syncthreads();

    const float m0 = sm_m[0], m1 = sm_m[1], m2 = sm_m[2], m3 = sm_m[3];
    const float s0 = sm_s[0], s1 = sm_s[1], s2 = sm_s[2], s3 = sm_s[3];
    for (int i = threadIdx.x; i < deg; i += 128) {
        float4 sc = *(const float4*)(g_scores + (size_t)(beg + i) * 4);
        float a = __expf(sc.x - m0) * s0 + __expf(sc.y - m1) * s1 +
                  __expf(sc.z - m2) * s2 + __expf(sc.w - m3) * s3;
        out[g_ceid[beg + i]] = 0.25f * a;
    }
}

// ---------------- launch ----------------
extern "C" void kernel_launch(void* const* d_in, const int* in_sizes, int n_in,
                              void* d_out, int out_size)
{
    const float* x    = (const float*)d_in[0];      // [N,128]
    const float* W    = (const float*)d_in[1];      // [1024,128]
    const float* bias = (const float*)d_in[2];      // [1024]
    const int*   ei   = (const int*)d_in[3];        // [2,E] int32 (jax x64 off)
    float* out = (float*)d_out;

    const int N = in_sizes[0] / 128;
    const int E = in_sizes[3] / 2;

    cudaFuncSetAttribute(gemm_qk_kernel,
                         cudaFuncAttributeMaxDynamicSharedMemorySize, 131072);

    dim3 gg(8, (N + 127) / 128);
    gemm_qk_kernel<<<gg, 256, 131072>>>(x, W, bias, N);

    const int nb = (N + SCAN_CHUNK - 1) / SCAN_CHUNK;
    zero_deg_kernel<<<(N + 255) / 256, 256>>>(N);
    hist_kernel<<<2048, 256>>>(ei, E);
    scan_reduce_kernel<<<nb, SCAN_BLK>>>(N);
    scan_top_kernel<<<1, 64>>>(nb, N);
    scan_write_kernel<<<nb, SCAN_BLK>>>(N);
    scatter_kernel<<<2048, 256>>>(ei, E);
    attn_kernel<<<N, 128>>>(out);
}